// round 13
// baseline (speedup 1.0000x reference)
#include <cuda_runtime.h>
#include <cstdint>

#define N_NODES 100000
#define N_EDGES 1600000
#define D_EDGE  50
#define SLOTS   64   // fixed eid slots per node (binomial max degree ~40)

// 1 if receivers buffer really holds int64, 0 if int32 (harness downcasts).
__device__ int g_idx_is_i64;

__device__ int g_cnt[N_NODES];                   // per-node degree
__device__ int g_slot[(size_t)N_NODES * SLOTS];  // eids grouped by receiver (25.6MB)
__device__ int g_ovf_n;                          // overflow count (expected 0)
__device__ int g_ovf[N_EDGES];                   // overflow eids (full-capacity safe)

__device__ __forceinline__ long long load_recv(const void* __restrict__ recv, int e) {
    return g_idx_is_i64 ? ((const long long*)recv)[e]
                        : (long long)((const int*)recv)[e];
}

// ---------------------------------------------------------------------------
// Kernel 1: init. Block 0 detects receivers dtype (first 2048 words as int64:
// true int64 indices all in [0,N_NODES); packed int32 pairs blow the range).
// All blocks zero the counters. Output needs no zeroing (gather writes it).
// ---------------------------------------------------------------------------
__global__ void init_kernel(const void* __restrict__ recv) {
    if (blockIdx.x == 0) {
        const long long* p64 = (const long long*)recv;
        int bad = 0;
        for (int i = threadIdx.x; i < 2048; i += blockDim.x) {
            long long v = p64[i];
            if (v < 0 || v >= N_NODES) bad = 1;
        }
        int any_bad = __syncthreads_or(bad);
        if (threadIdx.x == 0) { g_idx_is_i64 = any_bad ? 0 : 1; g_ovf_n = 0; }
    }
    for (int i = blockIdx.x * blockDim.x + threadIdx.x; i < N_NODES;
         i += gridDim.x * blockDim.x) {
        g_cnt[i] = 0;
    }
}

// ---------------------------------------------------------------------------
// Kernel 2: build slot lists, 4 independent edges per thread so the
// atomicAdd(result)->store chains overlap (ATOMG result latency ~318 cyc was
// the R9/R12 build bottleneck at MLP=1).
// ---------------------------------------------------------------------------
__global__ void build_kernel(const void* __restrict__ recv) {
    const int T = blockDim.x;
    const int base = blockIdx.x * T * 4 + threadIdx.x;

    int e[4], r[4], pos[4];
    bool ok[4];
#pragma unroll
    for (int k = 0; k < 4; k++) {
        e[k] = base + k * T;
        ok[k] = (e[k] < N_EDGES);
        if (ok[k]) {
            long long rr = load_recv(recv, e[k]);
            ok[k] = ((unsigned long long)rr < (unsigned long long)N_NODES);
            r[k] = (int)rr;
        }
    }
#pragma unroll
    for (int k = 0; k < 4; k++) {
        if (ok[k]) pos[k] = atomicAdd(&g_cnt[r[k]], 1);
    }
#pragma unroll
    for (int k = 0; k < 4; k++) {
        if (!ok[k]) continue;
        if (pos[k] < SLOTS) {
            g_slot[(size_t)r[k] * SLOTS + pos[k]] = e[k];
        } else {
            int o = atomicAdd(&g_ovf_n, 1);
            g_ovf[o] = e[k];
        }
    }
}

// ---------------------------------------------------------------------------
// Kernel 3: gather. One warp per node; lanes 0..24 own float2 dim-pairs.
// Slot line preloaded into 2 regs (coalesced), eids broadcast via shfl,
// 8-way unroll (~200 in-flight float2 per warp). A node whose raw count
// exceeds SLOTS additionally scans the overflow list (expected empty) --
// this subsumes the old overflow kernel at zero cost in the common case.
// Writes every output row exactly once -> no zero pass for d_out.
// ---------------------------------------------------------------------------
__global__ void gather_kernel(const float* __restrict__ edges,
                              const void* __restrict__ recv,
                              float* __restrict__ out) {
    const int warp = (blockIdx.x * blockDim.x + threadIdx.x) >> 5;
    const int lane = threadIdx.x & 31;
    if (warp >= N_NODES) return;

    const int cnt_raw = g_cnt[warp];
    const int cnt = (cnt_raw < SLOTS) ? cnt_raw : SLOTS;

    const int* slots = g_slot + (size_t)warp * SLOTS;
    const int e_lo = (lane < cnt) ? slots[lane] : 0;
    const int e_hi = (32 + lane < cnt) ? slots[32 + lane] : 0;

    const bool act = (lane < 25);
    const int d = 2 * lane;

    float2 a[8];
#pragma unroll
    for (int k = 0; k < 8; k++) a[k] = make_float2(0.f, 0.f);

    int j = 0;
    for (; j + 8 <= cnt; j += 8) {
        int ee[8];
#pragma unroll
        for (int k = 0; k < 8; k++) {
            int jj = j + k;
            ee[k] = __shfl_sync(0xffffffffu, (jj < 32) ? e_lo : e_hi, jj & 31);
        }
        if (act) {
#pragma unroll
            for (int k = 0; k < 8; k++) {
                float2 v = *reinterpret_cast<const float2*>(
                    edges + (size_t)ee[k] * D_EDGE + d);
                a[k].x += v.x; a[k].y += v.y;
            }
        }
    }
    for (; j + 4 <= cnt; j += 4) {
        int ee[4];
#pragma unroll
        for (int k = 0; k < 4; k++) {
            int jj = j + k;
            ee[k] = __shfl_sync(0xffffffffu, (jj < 32) ? e_lo : e_hi, jj & 31);
        }
        if (act) {
#pragma unroll
            for (int k = 0; k < 4; k++) {
                float2 v = *reinterpret_cast<const float2*>(
                    edges + (size_t)ee[k] * D_EDGE + d);
                a[k].x += v.x; a[k].y += v.y;
            }
        }
    }
    for (; j < cnt; j++) {
        int e = __shfl_sync(0xffffffffu, (j < 32) ? e_lo : e_hi, j & 31);
        if (act) {
            float2 v = *reinterpret_cast<const float2*>(
                edges + (size_t)e * D_EDGE + d);
            a[0].x += v.x; a[0].y += v.y;
        }
    }

    // Overflow fixup, fused: only nodes that actually overflowed scan the list.
    if (cnt_raw > SLOTS) {
        const int n = g_ovf_n;
        for (int o = 0; o < n; o++) {
            int e = g_ovf[o];
            if ((int)load_recv(recv, e) == warp && act) {
                float2 v = *reinterpret_cast<const float2*>(
                    edges + (size_t)e * D_EDGE + d);
                a[0].x += v.x; a[0].y += v.y;
            }
        }
    }

    if (act) {
        float2 r;
        r.x = ((a[0].x + a[1].x) + (a[2].x + a[3].x)) +
              ((a[4].x + a[5].x) + (a[6].x + a[7].x));
        r.y = ((a[0].y + a[1].y) + (a[2].y + a[3].y)) +
              ((a[4].y + a[5].y) + (a[6].y + a[7].y));
        *reinterpret_cast<float2*>(out + (size_t)warp * D_EDGE + d) = r;
    }
}

extern "C" void kernel_launch(void* const* d_in, const int* in_sizes, int n_in,
                              void* d_out, int out_size) {
    // Identify inputs by element count (robust to ordering):
    //   nodes: 800,000 f32 (unused) | edges: 80,000,000 f32 | receivers: 1,600,000
    const float* edges = nullptr;
    const void* receivers = nullptr;
    for (int i = 0; i < n_in; i++) {
        if (in_sizes[i] == N_EDGES * D_EDGE) {
            edges = (const float*)d_in[i];
        } else if (in_sizes[i] == N_EDGES) {
            receivers = d_in[i];
        }
    }
    float* out = (float*)d_out;

    const int T = 256;

    // 1) detect dtype + zero counters
    init_kernel<<<392, T>>>(receivers);

    // 2) build per-node slot lists (4 edges per thread for atomic-latency ILP)
    build_kernel<<<(N_EDGES + T * 4 - 1) / (T * 4), T>>>(receivers);

    // 3) gather (one warp per node) with fused overflow fixup
    gather_kernel<<<(N_NODES * 32 + T - 1) / T, T>>>(edges, receivers, out);
}